// round 10
// baseline (speedup 1.0000x reference)
#include <cuda_runtime.h>
#include <math.h>

// Problem constants
#define BSZ   4096
#define NCGC  2

#define MAIN_BLOCK 256   // 8 warps
#define WPB 8            // warps per block
#define GPW 2            // graphs per warp (sequential)

// Device-global scratch (allocation-free per harness rules)
// C[c][op][j][128]: j<2 -> A2[op]*p2[c][j] ; j in 2..4 -> A2[op]
__device__ float g_C[2 * 7 * 5 * 128];
__device__ float g_table[2 * 441 * 128]; // [c][key] layer-2 support, step nodes

// ---------------------------------------------------------------------------
// Kernel 1: fused precompute + table build (R6 design, best measured).
// One key per block, grid (441, 2). Weight matrices prefetched to L2 at entry.
// key = (op0*3 + fc0)*21 + (op1*3 + fc1), fc = min(f, 2).
// table[c][key] = relu(sup1b + A1[op0]*sup(fc0) + A1[op1]*sup(fc1)) @ W2
// ---------------------------------------------------------------------------
__global__ void build_kernel(
    const float* __restrict__ init_emb,   // (2,2,48)
    const float* __restrict__ other_emb,  // (2,1,48)
    const float* __restrict__ op_embs,    // (7,48)
    const float* __restrict__ Wx,         // (48,48)
    const float* __restrict__ bx,         // (48)
    const float* __restrict__ W1,         // (48,128)
    const float* __restrict__ Wa1,        // (48,128)
    const float* __restrict__ ba1,        // (128)
    const float* __restrict__ W2,         // (128,128)
    const float* __restrict__ Wa2,        // (48,128)
    const float* __restrict__ ba2)        // (128)
{
  const int d = threadIdx.x;
  const int c = blockIdx.y;

  // Fire-and-forget L2 prefetch of the weight matrices used late in the chain.
  // W2: 64KB = 512 lines; W1/Wa1: 24KB = 192 lines each.
  for (int i = d; i < 512; i += 128)
    asm volatile("prefetch.global.L2 [%0];" ::"l"(W2 + i * 32));
  for (int i = d; i < 192; i += 128) {
    asm volatile("prefetch.global.L2 [%0];" ::"l"(W1 + i * 32));
    asm volatile("prefetch.global.L2 [%0];" ::"l"(Wa1 + i * 32));
  }

  __shared__ float ope[7 * 48];
  __shared__ float y0[3 * 48];   // rows: 0,1 = init nodes, 2 = step node
  __shared__ float sh[128];

  for (int i = d; i < 7 * 48; i += 128) ope[i] = __ldg(&op_embs[i]);

  // One flat parallel phase for all three y0 rows (144 items over 128 threads)
  for (int it = d; it < 144; it += 128) {
    const int r = it / 48, h = it - r * 48;
    const float* e = (r < 2) ? (init_emb + (c * 2 + r) * 48)
                             : (other_emb + c * 48);
    float t = __ldg(&bx[h]);
#pragma unroll
    for (int k = 0; k < 48; ++k) t += __ldg(&e[k]) * __ldg(&Wx[k * 48 + h]);
    y0[it] = t;
  }
  __syncthreads();

  // Layer-1 support rows (shared W1-column loads across the 3 rows)
  float s0 = 0.f, s1 = 0.f, sb = 0.f;
#pragma unroll
  for (int h = 0; h < 48; ++h) {
    const float w = __ldg(&W1[h * 128 + d]);
    s0 += y0[h] * w;
    s1 += y0[48 + h] * w;
    sb += y0[96 + h] * w;
  }

  // A1 attention for this block's key ops only (op0, op1)
  const int key = blockIdx.x;
  const int sA = key / 21, sB = key - sA * 21;
  const int op0 = sA / 3, fc0 = sA - op0 * 3;
  const int op1 = sB / 3, fc1 = sB - op1 * 3;

  float a1v0, a1v1;
  {
    float acc0 = __ldg(&ba1[d]), acc1 = acc0;
#pragma unroll
    for (int k = 0; k < 48; ++k) {
      const float w = __ldg(&Wa1[k * 128 + d]);
      acc0 += ope[op0 * 48 + k] * w;
      acc1 += ope[op1 * 48 + k] * w;
    }
    a1v0 = (op0 == 0) ? 0.f : 1.f / (1.f + expf(-acc0));
    a1v1 = (op1 == 0) ? 0.f : 1.f / (1.f + expf(-acc1));
  }

  // Block 0 extras: A2 attention + p2 rows -> combined coefficient table C
  if (blockIdx.x == 0) {
    float a2v[7];
    {
      float acc[7];
#pragma unroll
      for (int op = 0; op < 7; ++op) acc[op] = __ldg(&ba2[d]);
      for (int k = 0; k < 48; ++k) {
        const float w = __ldg(&Wa2[k * 128 + d]);
#pragma unroll
        for (int op = 0; op < 7; ++op) acc[op] += ope[op * 48 + k] * w;
      }
      a2v[0] = 0.f;
#pragma unroll
      for (int op = 1; op < 7; ++op) a2v[op] = 1.f / (1.f + expf(-acc[op]));
    }
    // p2[j] = relu(sup1[c][j]) @ W2 for init nodes j=0,1
    float p2v[2];
#pragma unroll
    for (int j = 0; j < 2; ++j) {
      __syncthreads();
      sh[d] = fmaxf(j == 0 ? s0 : s1, 0.f);
      __syncthreads();
      float p0 = 0.f, p1 = 0.f, p2a = 0.f, p3 = 0.f;
#pragma unroll
      for (int h = 0; h < 128; h += 4) {
        p0 += sh[h]     * __ldg(&W2[(h)     * 128 + d]);
        p1 += sh[h + 1] * __ldg(&W2[(h + 1) * 128 + d]);
        p2a+= sh[h + 2] * __ldg(&W2[(h + 2) * 128 + d]);
        p3 += sh[h + 3] * __ldg(&W2[(h + 3) * 128 + d]);
      }
      p2v[j] = (p0 + p1) + (p2a + p3);
    }
    float* Cc = g_C + c * 7 * 5 * 128;
#pragma unroll
    for (int op = 0; op < 7; ++op) {
      Cc[(op * 5 + 0) * 128 + d] = a2v[op] * p2v[0];
      Cc[(op * 5 + 1) * 128 + d] = a2v[op] * p2v[1];
      Cc[(op * 5 + 2) * 128 + d] = a2v[op];
      Cc[(op * 5 + 3) * 128 + d] = a2v[op];
      Cc[(op * 5 + 4) * 128 + d] = a2v[op];
    }
  }

  // This block's single key
  {
    const float v0 = (fc0 == 0) ? s0 : (fc0 == 1) ? s1 : sb;
    const float v1 = (fc1 == 0) ? s0 : (fc1 == 1) ? s1 : sb;
    const float y = sb + a1v0 * v0 + a1v1 * v1;
    __syncthreads();
    sh[d] = fmaxf(y, 0.f);
    __syncthreads();
    float a0 = 0.f, a1_ = 0.f, a2 = 0.f, a3 = 0.f;
#pragma unroll
    for (int h = 0; h < 128; h += 4) {
      a0  += sh[h]     * __ldg(&W2[(h)     * 128 + d]);
      a1_ += sh[h + 1] * __ldg(&W2[(h + 1) * 128 + d]);
      a2  += sh[h + 2] * __ldg(&W2[(h + 2) * 128 + d]);
      a3  += sh[h + 3] * __ldg(&W2[(h + 3) * 128 + d]);
    }
    g_table[(c * 441 + key) * 128 + d] = (a0 + a1_) + (a2 + a3);
  }

#if __CUDA_ARCH__ >= 900
  cudaTriggerProgrammaticLaunchCompletion();
#endif
}

// ---------------------------------------------------------------------------
// Kernel 2 (PDL consumer): 2 graphs per warp, sequential; lane owns 4 dims.
// 512 blocks @ <=64 regs -> 4 blocks/SM -> single wave (592 slots >= 512).
// Pre-sync phase loads BOTH graphs' archs and reduces them to 8 key ints
// (overlapped with build via PDL). Per edge: one LDG.128 from C, then add
// (f<2) or FMA with a register-selected table row.
// ---------------------------------------------------------------------------
__global__ void __launch_bounds__(MAIN_BLOCK, 4)
gcn_main_kernel(const int* __restrict__ archs, float* __restrict__ out) {
  const int tid  = threadIdx.x;
  const int lane = tid & 31;
  const int w    = tid >> 5;

  const int task = blockIdx.x * WPB + w;   // 0..4095 (2 graphs each)
  const int g0   = task * GPW;             // flat graph index base
  const int c    = g0 >> 12;               // warp-uniform (both graphs same c)

  // ---- pre-dependency phase: arch loads + key computation, both graphs ----
  int keys[GPW][4], bb[GPW];
#pragma unroll
  for (int g = 0; g < GPW; ++g) {
    const int b = (g0 + g) & (BSZ - 1);
    bb[g] = b;
    const int4* a = (const int4*)(archs + (size_t)(b * NCGC + c) * 16);
    const int4 fA = __ldg(a);      // f[0..3]
    const int4 fB = __ldg(a + 1);  // f[4..7]
    const int4 oA = __ldg(a + 2);  // op[0..3]
    const int4 oB = __ldg(a + 3);  // op[4..7]
    keys[g][0] = ((oA.x * 3 + min(fA.x, 2)) * 21 + oA.y * 3 + min(fA.y, 2)) * 40
               + (oA.x * 5 + min(fA.x, 4)) * 0;   // key
    keys[g][0] = (oA.x * 3 + min(fA.x, 2)) * 21 + oA.y * 3 + min(fA.y, 2);
    keys[g][1] = (oA.z * 3 + min(fA.z, 2)) * 21 + oA.w * 3 + min(fA.w, 2);
    keys[g][2] = (oB.x * 3 + min(fB.x, 2)) * 21 + oB.y * 3 + min(fB.y, 2);
    keys[g][3] = (oB.z * 3 + min(fB.z, 2)) * 21 + oB.w * 3 + min(fB.w, 2);
    // Pack edge (op, f) pairs for the epilogue: op in [0,7), f in [0,5)
    // stored as o*5+min(f,4) per edge, 8 edges in two ints
    bb[g] = b;
    keys[g][0] |= ((oA.x * 5 + min(fA.x, 4)) << 16);
    keys[g][1] |= ((oA.y * 5 + min(fA.y, 4)) << 16) | ((oA.z * 5 + min(fA.z, 4)) << 24);
    keys[g][2] |= ((oA.w * 5 + min(fA.w, 4)) << 16) | ((oB.x * 5 + min(fB.x, 4)) << 24);
    keys[g][3] |= ((oB.y * 5 + min(fB.y, 4)) << 16) | ((oB.z * 5 + min(fB.z, 4)) << 24);
    bb[g] |= ((oB.w * 5 + min(fB.w, 4)) << 16);
  }

  // ---- wait for build_kernel's writes ----
#if __CUDA_ARCH__ >= 900
  cudaGridDependencySynchronize();
#endif

  const float* __restrict__ tab = g_table + (size_t)c * 441 * 128;
  const float4* __restrict__ C4 = (const float4*)(g_C + c * 7 * 5 * 128);

#pragma unroll
  for (int g = 0; g < GPW; ++g) {
    const int k0 = keys[g][0] & 0xFFFF;
    const int k1 = keys[g][1] & 0xFFFF;
    const int k2 = keys[g][2] & 0xFFFF;
    const int k3 = keys[g][3] & 0xFFFF;

    const float4 r0 = __ldg((const float4*)(tab + k0 * 128) + lane);
    const float4 r1 = __ldg((const float4*)(tab + k1 * 128) + lane);
    const float4 r2 = __ldg((const float4*)(tab + k2 * 128) + lane);
    const float4 r3 = __ldg((const float4*)(tab + k3 * 128) + lane);

    float4 accA, accB;
    accA.x = r0.x + r1.x;  accB.x = r2.x + r3.x;
    accA.y = r0.y + r1.y;  accB.y = r2.y + r3.y;
    accA.z = r0.z + r1.z;  accB.z = r2.z + r3.z;
    accA.w = r0.w + r1.w;  accB.w = r2.w + r3.w;

    // Unpack 8 edge codes (o*5+fc each; fc = min(f,4))
    const int e0 = (keys[g][0] >> 16) & 0xFF;
    const int e1 = (keys[g][1] >> 16) & 0xFF;
    const int e2 = (keys[g][1] >> 24) & 0xFF;
    const int e3 = (keys[g][2] >> 16) & 0xFF;
    const int e4 = (keys[g][2] >> 24) & 0xFF;
    const int e5 = (keys[g][3] >> 16) & 0xFF;
    const int e6 = (keys[g][3] >> 24) & 0xFF;
    const int e7 = (bb[g] >> 16) & 0xFF;
    const int b  = bb[g] & 0xFFFF;

#define EDGE(ACC, e)                                                   \
    {                                                                  \
      const int fc = (e) - ((e) / 5) * 5;                              \
      const float4 cr = __ldg(&C4[(e) * 32 + lane]);                   \
      if (fc < 2) {                                                    \
        ACC.x += cr.x; ACC.y += cr.y; ACC.z += cr.z; ACC.w += cr.w;    \
      } else {                                                         \
        const float4 rv = (fc == 2) ? r0 : ((fc == 3) ? r1 : r2);      \
        ACC.x += cr.x * rv.x; ACC.y += cr.y * rv.y;                    \
        ACC.z += cr.z * rv.z; ACC.w += cr.w * rv.w;                    \
      }                                                                \
    }

    EDGE(accA, e0); EDGE(accB, e1);
    EDGE(accA, e2); EDGE(accB, e3);
    EDGE(accA, e4); EDGE(accB, e5);
    EDGE(accA, e6); EDGE(accB, e7);
#undef EDGE

    float4 res;
    res.x = (accA.x + accB.x) * 0.25f;
    res.y = (accA.y + accB.y) * 0.25f;
    res.z = (accA.z + accB.z) * 0.25f;
    res.w = (accA.w + accB.w) * 0.25f;
    ((float4*)(out + (size_t)(b * NCGC + c) * 128))[lane] = res;
  }
}

// ---------------------------------------------------------------------------
extern "C" void kernel_launch(void* const* d_in, const int* in_sizes, int n_in,
                              void* d_out, int out_size) {
  const int*   archs     = (const int*)d_in[0];
  const float* init_emb  = (const float*)d_in[1];
  const float* other_emb = (const float*)d_in[2];
  const float* op_embs   = (const float*)d_in[3];
  const float* Wx        = (const float*)d_in[4];
  const float* bx        = (const float*)d_in[5];
  const float* W1        = (const float*)d_in[6];
  const float* Wa1       = (const float*)d_in[7];
  const float* ba1       = (const float*)d_in[8];
  const float* W2        = (const float*)d_in[9];
  const float* Wa2       = (const float*)d_in[10];
  const float* ba2       = (const float*)d_in[11];
  float* out = (float*)d_out;

  build_kernel<<<dim3(441, NCGC), 128>>>(init_emb, other_emb, op_embs, Wx, bx,
                                         W1, Wa1, ba1, W2, Wa2, ba2);

  // Programmatic Dependent Launch: main starts while build runs; each thread
  // blocks at cudaGridDependencySynchronize until build completes.
  cudaLaunchConfig_t cfg = {};
  cfg.gridDim  = dim3(BSZ * NCGC / GPW / WPB);   // 512 blocks -> single wave
  cfg.blockDim = dim3(MAIN_BLOCK);
  cudaLaunchAttribute attr[1];
  attr[0].id = cudaLaunchAttributeProgrammaticStreamSerialization;
  attr[0].val.programmaticStreamSerializationAllowed = 1;
  cfg.attrs = attr;
  cfg.numAttrs = 1;
  cudaLaunchKernelEx(&cfg, gcn_main_kernel, archs, out);
}

// round 11
// speedup vs baseline: 1.2020x; 1.2020x over previous
#include <cuda_runtime.h>
#include <math.h>

// Problem constants
#define BSZ   4096
#define NCGC  2

#define MAIN_BLOCK 256   // 8 warps
#define WPB 8            // warps per block (1 graph per warp)

// Device-global scratch (allocation-free per harness rules)
// C[c][op][j][128]: j<2 -> A2[op]*p2[c][j] ; j in 2..4 -> A2[op]
__device__ float g_C[2 * 7 * 5 * 128];
__device__ float g_table[2 * 441 * 128]; // [c][key] layer-2 support, step nodes

// ---------------------------------------------------------------------------
// Kernel 1: fused precompute + table build. TWO keys per block, grid (221, 2)
// (same per-SM block count as the proven 441-grid; W2 read once per 2 keys ->
// L2 traffic halved). PDL trigger fires at KERNEL ENTRY so the main grid
// schedules and runs its pre-sync phase concurrently with build.
// key = (op0*3 + fc0)*21 + (op1*3 + fc1), fc = min(f, 2).
// table[c][key] = relu(sup1b + A1[op0]*sup(fc0) + A1[op1]*sup(fc1)) @ W2
// ---------------------------------------------------------------------------
__global__ void build_kernel(
    const float* __restrict__ init_emb,   // (2,2,48)
    const float* __restrict__ other_emb,  // (2,1,48)
    const float* __restrict__ op_embs,    // (7,48)
    const float* __restrict__ Wx,         // (48,48)
    const float* __restrict__ bx,         // (48)
    const float* __restrict__ W1,         // (48,128)
    const float* __restrict__ Wa1,        // (48,128)
    const float* __restrict__ ba1,        // (128)
    const float* __restrict__ W2,         // (128,128)
    const float* __restrict__ Wa2,        // (48,128)
    const float* __restrict__ ba2)        // (128)
{
#if __CUDA_ARCH__ >= 900
  // Early trigger: dependent grid may begin scheduling + pre-sync work now.
  // Its cudaGridDependencySynchronize still waits for THIS grid's completion.
  cudaTriggerProgrammaticLaunchCompletion();
#endif

  const int d = threadIdx.x;
  const int c = blockIdx.y;

  __shared__ float ope[7 * 48];
  __shared__ float y0[3 * 48];   // rows: 0,1 = init nodes, 2 = step node
  __shared__ float sh[2][128];   // the 2 y1 key rows
  __shared__ float shp[128];     // lead-block p2 scratch

  for (int i = d; i < 7 * 48; i += 128) ope[i] = __ldg(&op_embs[i]);

  // One flat parallel phase for all three y0 rows (144 items over 128 threads)
  for (int it = d; it < 144; it += 128) {
    const int r = it / 48, h = it - r * 48;
    const float* e = (r < 2) ? (init_emb + (c * 2 + r) * 48)
                             : (other_emb + c * 48);
    float t = __ldg(&bx[h]);
#pragma unroll
    for (int k = 0; k < 48; ++k) t += __ldg(&e[k]) * __ldg(&Wx[k * 48 + h]);
    y0[it] = t;
  }
  __syncthreads();

  // Layer-1 support rows (shared W1-column loads across the 3 rows)
  float s0 = 0.f, s1 = 0.f, sb = 0.f;
#pragma unroll
  for (int h = 0; h < 48; ++h) {
    const float w = __ldg(&W1[h * 128 + d]);
    s0 += y0[h] * w;
    s1 += y0[48 + h] * w;
    sb += y0[96 + h] * w;
  }

  // This block's two keys
  const int keyA = blockIdx.x * 2;
  const int keyB_raw = keyA + 1;
  const bool validB = (keyB_raw < 441);
  const int keyB = validB ? keyB_raw : 440;

  const int sAa = keyA / 21, sBa = keyA - sAa * 21;
  const int opA0 = sAa / 3, fcA0 = sAa - opA0 * 3;
  const int opA1 = sBa / 3, fcA1 = sBa - opA1 * 3;
  const int sAb = keyB / 21, sBb = keyB - sAb * 21;
  const int opB0 = sAb / 3, fcB0 = sAb - opB0 * 3;
  const int opB1 = sBb / 3, fcB1 = sBb - opB1 * 3;

  // A1 attention for the 4 (op) slots of the two keys
  float aA0, aA1, aB0, aB1;
  {
    const float bias = __ldg(&ba1[d]);
    float c0 = bias, c1 = bias, c2 = bias, c3 = bias;
#pragma unroll
    for (int k = 0; k < 48; ++k) {
      const float w = __ldg(&Wa1[k * 128 + d]);
      c0 += ope[opA0 * 48 + k] * w;
      c1 += ope[opA1 * 48 + k] * w;
      c2 += ope[opB0 * 48 + k] * w;
      c3 += ope[opB1 * 48 + k] * w;
    }
    aA0 = (opA0 == 0) ? 0.f : 1.f / (1.f + expf(-c0));
    aA1 = (opA1 == 0) ? 0.f : 1.f / (1.f + expf(-c1));
    aB0 = (opB0 == 0) ? 0.f : 1.f / (1.f + expf(-c2));
    aB1 = (opB1 == 0) ? 0.f : 1.f / (1.f + expf(-c3));
  }

  // Lead block extras: A2 attention + p2 rows -> combined coefficient table C
  if (blockIdx.x == 0) {
    float a2v[7];
    {
      float acc[7];
#pragma unroll
      for (int op = 0; op < 7; ++op) acc[op] = __ldg(&ba2[d]);
      for (int k = 0; k < 48; ++k) {
        const float w = __ldg(&Wa2[k * 128 + d]);
#pragma unroll
        for (int op = 0; op < 7; ++op) acc[op] += ope[op * 48 + k] * w;
      }
      a2v[0] = 0.f;
#pragma unroll
      for (int op = 1; op < 7; ++op) a2v[op] = 1.f / (1.f + expf(-acc[op]));
    }
    // p2[j] = relu(sup1[c][j]) @ W2 for init nodes j=0,1
    float p2v[2];
#pragma unroll
    for (int j = 0; j < 2; ++j) {
      __syncthreads();
      shp[d] = fmaxf(j == 0 ? s0 : s1, 0.f);
      __syncthreads();
      float p0 = 0.f, p1 = 0.f, p2a = 0.f, p3 = 0.f;
#pragma unroll
      for (int h = 0; h < 128; h += 4) {
        p0 += shp[h]     * __ldg(&W2[(h)     * 128 + d]);
        p1 += shp[h + 1] * __ldg(&W2[(h + 1) * 128 + d]);
        p2a+= shp[h + 2] * __ldg(&W2[(h + 2) * 128 + d]);
        p3 += shp[h + 3] * __ldg(&W2[(h + 3) * 128 + d]);
      }
      p2v[j] = (p0 + p1) + (p2a + p3);
    }
    float* Cc = g_C + c * 7 * 5 * 128;
#pragma unroll
    for (int op = 0; op < 7; ++op) {
      Cc[(op * 5 + 0) * 128 + d] = a2v[op] * p2v[0];
      Cc[(op * 5 + 1) * 128 + d] = a2v[op] * p2v[1];
      Cc[(op * 5 + 2) * 128 + d] = a2v[op];
      Cc[(op * 5 + 3) * 128 + d] = a2v[op];
      Cc[(op * 5 + 4) * 128 + d] = a2v[op];
    }
  }

  // y1 rows for both keys
  {
    const float vA0 = (fcA0 == 0) ? s0 : (fcA0 == 1) ? s1 : sb;
    const float vA1 = (fcA1 == 0) ? s0 : (fcA1 == 1) ? s1 : sb;
    const float vB0 = (fcB0 == 0) ? s0 : (fcB0 == 1) ? s1 : sb;
    const float vB1 = (fcB1 == 0) ? s0 : (fcB1 == 1) ? s1 : sb;
    __syncthreads();
    sh[0][d] = fmaxf(sb + aA0 * vA0 + aA1 * vA1, 0.f);
    sh[1][d] = fmaxf(sb + aB0 * vB0 + aB1 * vB1, 0.f);
    __syncthreads();
  }

  // Shared-W2 GEMM for the two keys: each W2 element read once per block.
  float a0 = 0.f, a1_ = 0.f, a2 = 0.f, a3 = 0.f;   // key A (4-way h-split)
  float b0 = 0.f, b1_ = 0.f, b2 = 0.f, b3 = 0.f;   // key B
#pragma unroll
  for (int h = 0; h < 128; h += 4) {
    const float w0 = __ldg(&W2[(h)     * 128 + d]);
    const float w1 = __ldg(&W2[(h + 1) * 128 + d]);
    const float w2 = __ldg(&W2[(h + 2) * 128 + d]);
    const float w3 = __ldg(&W2[(h + 3) * 128 + d]);
    a0  += sh[0][h]     * w0;  b0  += sh[1][h]     * w0;
    a1_ += sh[0][h + 1] * w1;  b1_ += sh[1][h + 1] * w1;
    a2  += sh[0][h + 2] * w2;  b2  += sh[1][h + 2] * w2;
    a3  += sh[0][h + 3] * w3;  b3  += sh[1][h + 3] * w3;
  }
  g_table[(c * 441 + keyA) * 128 + d] = (a0 + a1_) + (a2 + a3);
  if (validB)
    g_table[(c * 441 + keyB) * 128 + d] = (b0 + b1_) + (b2 + b3);
}

// ---------------------------------------------------------------------------
// Kernel 2 (PDL consumer, R9-proven): one warp per graph, lane owns 4 dims.
// Pre-sync phase (overlapped with build via early trigger): arch loads + keys.
// Per edge: one LDG.128 from C, then add (f<2) or FMA with register-selected
// table row. Two independent accumulators.
// ---------------------------------------------------------------------------
__global__ void __launch_bounds__(MAIN_BLOCK)
gcn_main_kernel(const int* __restrict__ archs, float* __restrict__ out) {
  const int tid  = threadIdx.x;
  const int lane = tid & 31;
  const int w    = tid >> 5;

  const int task = blockIdx.x * WPB + w;   // 0..8191 (one graph each)
  const int c    = task >> 12;             // warp-uniform
  const int b    = task & (BSZ - 1);

  // ---- pre-dependency phase: arch loads + key computation ----
  const int4* a = (const int4*)(archs + (size_t)(b * NCGC + c) * 16);
  const int4 fA = __ldg(a);      // f[0..3]
  const int4 fB = __ldg(a + 1);  // f[4..7]
  const int4 oA = __ldg(a + 2);  // op[0..3]
  const int4 oB = __ldg(a + 3);  // op[4..7]

  const int k0 = (oA.x * 3 + min(fA.x, 2)) * 21 + oA.y * 3 + min(fA.y, 2);
  const int k1 = (oA.z * 3 + min(fA.z, 2)) * 21 + oA.w * 3 + min(fA.w, 2);
  const int k2 = (oB.x * 3 + min(fB.x, 2)) * 21 + oB.y * 3 + min(fB.y, 2);
  const int k3 = (oB.z * 3 + min(fB.z, 2)) * 21 + oB.w * 3 + min(fB.w, 2);

  // ---- wait for build_kernel's writes ----
#if __CUDA_ARCH__ >= 900
  cudaGridDependencySynchronize();
#endif

  const float* __restrict__ tab = g_table + (size_t)c * 441 * 128;

  // Issue all 4 gathers immediately (independent LDG.128s)
  const float4 r0 = __ldg((const float4*)(tab + k0 * 128) + lane);
  const float4 r1 = __ldg((const float4*)(tab + k1 * 128) + lane);
  const float4 r2 = __ldg((const float4*)(tab + k2 * 128) + lane);
  const float4 r3 = __ldg((const float4*)(tab + k3 * 128) + lane);

  // Two independent accumulators to halve the dependency chain
  float4 accA, accB;
  accA.x = r0.x + r1.x;  accB.x = r2.x + r3.x;
  accA.y = r0.y + r1.y;  accB.y = r2.y + r3.y;
  accA.z = r0.z + r1.z;  accB.z = r2.z + r3.z;
  accA.w = r0.w + r1.w;  accB.w = r2.w + r3.w;

  const float4* __restrict__ C4 = (const float4*)(g_C + c * 7 * 5 * 128);

#define EDGE(ACC, o, f)                                                \
  {                                                                    \
    const float4 cr = __ldg(&C4[((o) * 5 + (f)) * 32 + lane]);         \
    if ((f) < 2) {                                                     \
      ACC.x += cr.x; ACC.y += cr.y; ACC.z += cr.z; ACC.w += cr.w;      \
    } else {                                                           \
      const float4 rv = ((f) == 2) ? r0 : (((f) == 3) ? r1 : r2);      \
      ACC.x += cr.x * rv.x; ACC.y += cr.y * rv.y;                      \
      ACC.z += cr.z * rv.z; ACC.w += cr.w * rv.w;                      \
    }                                                                  \
  }

  EDGE(accA, oA.x, fA.x); EDGE(accB, oA.y, fA.y);
  EDGE(accA, oA.z, fA.z); EDGE(accB, oA.w, fA.w);
  EDGE(accA, oB.x, fB.x); EDGE(accB, oB.y, fB.y);
  EDGE(accA, oB.z, fB.z); EDGE(accB, oB.w, fB.w);
#undef EDGE

  float4 res;
  res.x = (accA.x + accB.x) * 0.25f;
  res.y = (accA.y + accB.y) * 0.25f;
  res.z = (accA.z + accB.z) * 0.25f;
  res.w = (accA.w + accB.w) * 0.25f;
  ((float4*)(out + (size_t)(b * NCGC + c) * 128))[lane] = res;
}

// ---------------------------------------------------------------------------
extern "C" void kernel_launch(void* const* d_in, const int* in_sizes, int n_in,
                              void* d_out, int out_size) {
  const int*   archs     = (const int*)d_in[0];
  const float* init_emb  = (const float*)d_in[1];
  const float* other_emb = (const float*)d_in[2];
  const float* op_embs   = (const float*)d_in[3];
  const float* Wx        = (const float*)d_in[4];
  const float* bx        = (const float*)d_in[5];
  const float* W1        = (const float*)d_in[6];
  const float* Wa1       = (const float*)d_in[7];
  const float* ba1       = (const float*)d_in[8];
  const float* W2        = (const float*)d_in[9];
  const float* Wa2       = (const float*)d_in[10];
  const float* ba2       = (const float*)d_in[11];
  float* out = (float*)d_out;

  build_kernel<<<dim3(221, NCGC), 128>>>(init_emb, other_emb, op_embs, Wx, bx,
                                         W1, Wa1, ba1, W2, Wa2, ba2);

  // Programmatic Dependent Launch: build triggers at ENTRY, so main's blocks
  // schedule and execute their pre-sync phase while build runs; each thread
  // then blocks at cudaGridDependencySynchronize until build fully completes.
  cudaLaunchConfig_t cfg = {};
  cfg.gridDim  = dim3(BSZ * NCGC / WPB);   // 1024 blocks
  cfg.blockDim = dim3(MAIN_BLOCK);
  cudaLaunchAttribute attr[1];
  attr[0].id = cudaLaunchAttributeProgrammaticStreamSerialization;
  attr[0].val.programmaticStreamSerializationAllowed = 1;
  cfg.attrs = attr;
  cfg.numAttrs = 1;
  cudaLaunchKernelEx(&cfg, gcn_main_kernel, archs, out);
}